// round 3
// baseline (speedup 1.0000x reference)
#include <cuda_runtime.h>

// ---------------------------------------------------------------------------
// CausalSelfAttention: y = softmax_causal((xWqkv).q @ .k^T / sqrt(Dh)) @ .v  @ Wout
// B=4, T=2048, C=1024, H=16, Dh=64. Full fp32 baseline (CUDA-core FFMA).
// ---------------------------------------------------------------------------

#define D_MODEL 1024
#define N_HEADS 16
#define HEAD_DIM 64
#define BATCH 4
#define SEQ 2048
#define MTOT (BATCH * SEQ)   // 8192 rows
#define C3 (3 * D_MODEL)     // 3072

// Scratch (allocation-free rule: __device__ globals)
__device__ float g_qkv[(size_t)MTOT * C3];      // [B*T, 3C]   96 MB
__device__ float g_y[(size_t)MTOT * D_MODEL];   // [B*T, C]    32 MB

// ---------------------------------------------------------------------------
// SGEMM: C[M,N] = A[M,K] @ B[K,N] + bias[N]
// 128x128 block tile, BK=8, 256 threads, 8x8 per-thread microtile.
// All dims are multiples of 128/8 here, so no edge handling.
// ---------------------------------------------------------------------------
__device__ __forceinline__ void sgemm_body(const float* __restrict__ A,
                                           const float* __restrict__ B,
                                           const float* __restrict__ bias,
                                           float* __restrict__ C,
                                           int N, int K)
{
    __shared__ float As[8][128];   // As[k][m] (A tile transposed)
    __shared__ float Bs[8][128];   // Bs[k][n]

    const int tid = threadIdx.x;
    const int bx = blockIdx.x;     // N tile
    const int by = blockIdx.y;     // M tile

    const int aRow = tid >> 1;            // 0..127
    const int aCol = (tid & 1) << 2;      // 0 or 4
    const int bRow = tid >> 5;            // 0..7
    const int bCol = (tid & 31) << 2;     // 0..124

    const int tx = tid & 15;
    const int ty = tid >> 4;

    const float* Ap = A + (size_t)(by * 128 + aRow) * K + aCol;
    const float* Bp = B + (size_t)bRow * N + bx * 128 + bCol;

    float acc[8][8];
#pragma unroll
    for (int i = 0; i < 8; i++)
#pragma unroll
        for (int j = 0; j < 8; j++) acc[i][j] = 0.0f;

    for (int k0 = 0; k0 < K; k0 += 8) {
        float4 a = *(const float4*)(Ap + k0);
        float4 b4 = *(const float4*)(Bp + (size_t)k0 * N);
        As[aCol + 0][aRow] = a.x;
        As[aCol + 1][aRow] = a.y;
        As[aCol + 2][aRow] = a.z;
        As[aCol + 3][aRow] = a.w;
        *(float4*)&Bs[bRow][bCol] = b4;
        __syncthreads();

#pragma unroll
        for (int kk = 0; kk < 8; kk++) {
            float ar[8], br[8];
            *(float4*)&ar[0] = *(const float4*)&As[kk][ty * 4];
            *(float4*)&ar[4] = *(const float4*)&As[kk][64 + ty * 4];
            *(float4*)&br[0] = *(const float4*)&Bs[kk][tx * 4];
            *(float4*)&br[4] = *(const float4*)&Bs[kk][64 + tx * 4];
#pragma unroll
            for (int i = 0; i < 8; i++)
#pragma unroll
                for (int j = 0; j < 8; j++)
                    acc[i][j] += ar[i] * br[j];
        }
        __syncthreads();
    }

    // epilogue with bias
#pragma unroll
    for (int i = 0; i < 8; i++) {
        int m = by * 128 + ((i < 4) ? (ty * 4 + i) : (64 + ty * 4 + (i - 4)));
#pragma unroll
        for (int jh = 0; jh < 2; jh++) {
            int n = bx * 128 + jh * 64 + tx * 4;
            float4 bb = *(const float4*)&bias[n];
            float4 r;
            r.x = acc[i][jh * 4 + 0] + bb.x;
            r.y = acc[i][jh * 4 + 1] + bb.y;
            r.z = acc[i][jh * 4 + 2] + bb.z;
            r.w = acc[i][jh * 4 + 3] + bb.w;
            *(float4*)&C[(size_t)m * N + n] = r;
        }
    }
}

__global__ __launch_bounds__(256) void qkv_gemm_kernel(const float* __restrict__ x,
                                                       const float* __restrict__ W,
                                                       const float* __restrict__ bias)
{
    sgemm_body(x, W, bias, g_qkv, C3, D_MODEL);
}

__global__ __launch_bounds__(256) void out_gemm_kernel(const float* __restrict__ W,
                                                       const float* __restrict__ bias,
                                                       float* __restrict__ out)
{
    sgemm_body(g_y, W, bias, out, D_MODEL, D_MODEL);
}

// ---------------------------------------------------------------------------
// Flash attention (fp32, online softmax).
// Grid: (T/64, B*H). Block: 256 threads = 16x16 grid of 4x4 microtiles.
// Smem tiles (pad 68 floats/row -> 16B-aligned float4 rows, reduced conflicts):
//   Qt[d][i], Kt[d][j]  (transposed: contiguous over row index for float4 LDS)
//   Vs[j][d], Ps[i][j]
// ---------------------------------------------------------------------------
#define APAD 68
#define ATTN_SMEM_BYTES (4 * 64 * APAD * (int)sizeof(float))  // 69632

__global__ __launch_bounds__(256) void attn_kernel()
{
    extern __shared__ float sm[];
    float* Qt = sm;                  // [64][APAD]
    float* Kt = Qt + 64 * APAD;
    float* Vs = Kt + 64 * APAD;
    float* Ps = Vs + 64 * APAD;

    const int qt = blockIdx.x;
    const int b  = blockIdx.y >> 4;
    const int h  = blockIdx.y & 15;
    const int tid = threadIdx.x;
    const int tx = tid & 15;         // column group (j / d dim)
    const int ty = tid >> 4;         // row group   (i dim)
    const int qbase = qt * 64;

    const float* qkvb = g_qkv + (size_t)b * SEQ * C3 + h * HEAD_DIM;

    // Load Q tile transposed: Qt[d][i]
    for (int idx = tid; idx < 64 * 64; idx += 256) {
        int i = idx >> 6, d = idx & 63;
        Qt[d * APAD + i] = qkvb[(size_t)(qbase + i) * C3 + d];
    }

    float m[4], l[4], o[4][4];
#pragma unroll
    for (int r = 0; r < 4; r++) {
        m[r] = -1e30f; l[r] = 0.0f;
#pragma unroll
        for (int c = 0; c < 4; c++) o[r][c] = 0.0f;
    }

    for (int kt = 0; kt <= qt; ++kt) {
        const int kbase = kt * 64;
        __syncthreads();   // protect Kt/Vs/Ps from previous iteration's readers
        for (int idx = tid; idx < 64 * 64; idx += 256) {
            int j = idx >> 6, d = idx & 63;
            size_t off = (size_t)(kbase + j) * C3 + d;
            Kt[d * APAD + j] = qkvb[off + D_MODEL];       // K
            Vs[j * APAD + d] = qkvb[off + 2 * D_MODEL];   // V
        }
        __syncthreads();

        // S = Q @ K^T  (4x4 per thread: rows 4ty.., cols 4tx..)
        float s[4][4];
#pragma unroll
        for (int r = 0; r < 4; r++)
#pragma unroll
            for (int c = 0; c < 4; c++) s[r][c] = 0.0f;

#pragma unroll 8
        for (int d = 0; d < 64; ++d) {
            float4 qv = *(const float4*)&Qt[d * APAD + ty * 4];
            float4 kv = *(const float4*)&Kt[d * APAD + tx * 4];
            float qa[4] = {qv.x, qv.y, qv.z, qv.w};
            float ka[4] = {kv.x, kv.y, kv.z, kv.w};
#pragma unroll
            for (int r = 0; r < 4; r++)
#pragma unroll
                for (int c = 0; c < 4; c++)
                    s[r][c] += qa[r] * ka[c];
        }

        const float scale = 0.125f;  // 1/sqrt(64)
        if (kt == qt) {
            // diagonal tile: causal mask on local indices
#pragma unroll
            for (int r = 0; r < 4; r++)
#pragma unroll
                for (int c = 0; c < 4; c++)
                    s[r][c] = (tx * 4 + c > ty * 4 + r) ? -1e30f : s[r][c] * scale;
        } else {
#pragma unroll
            for (int r = 0; r < 4; r++)
#pragma unroll
                for (int c = 0; c < 4; c++)
                    s[r][c] *= scale;
        }

        // Online softmax: 16 threads with the same ty own a row; shfl over tx
#pragma unroll
        for (int r = 0; r < 4; r++) {
            float tm = fmaxf(fmaxf(s[r][0], s[r][1]), fmaxf(s[r][2], s[r][3]));
#pragma unroll
            for (int off = 8; off >= 1; off >>= 1)
                tm = fmaxf(tm, __shfl_xor_sync(0xffffffffu, tm, off));
            float nm = fmaxf(m[r], tm);
            float corr = __expf(m[r] - nm);
            m[r] = nm;
            float rs = 0.0f;
#pragma unroll
            for (int c = 0; c < 4; c++) {
                float p = __expf(s[r][c] - nm);
                s[r][c] = p;
                rs += p;
            }
#pragma unroll
            for (int off = 8; off >= 1; off >>= 1)
                rs += __shfl_xor_sync(0xffffffffu, rs, off);
            l[r] = l[r] * corr + rs;
#pragma unroll
            for (int c = 0; c < 4; c++) o[r][c] *= corr;
        }

        // Stage P to smem, then O += P @ V
#pragma unroll
        for (int r = 0; r < 4; r++)
#pragma unroll
            for (int c = 0; c < 4; c++)
                Ps[(ty * 4 + r) * APAD + tx * 4 + c] = s[r][c];
        __syncthreads();

#pragma unroll 8
        for (int j = 0; j < 64; ++j) {
            float4 vv = *(const float4*)&Vs[j * APAD + tx * 4];
            float va[4] = {vv.x, vv.y, vv.z, vv.w};
#pragma unroll
            for (int r = 0; r < 4; r++) {
                float p = Ps[(ty * 4 + r) * APAD + j];
#pragma unroll
                for (int c = 0; c < 4; c++)
                    o[r][c] += p * va[c];
            }
        }
    }

    // Finalize and store in [B, T, H*Dh] layout (matches reference reshape)
    float* yb = g_y + (size_t)b * SEQ * D_MODEL + h * HEAD_DIM;
#pragma unroll
    for (int r = 0; r < 4; r++) {
        float inv = 1.0f / l[r];
        float4 out4;
        out4.x = o[r][0] * inv;
        out4.y = o[r][1] * inv;
        out4.z = o[r][2] * inv;
        out4.w = o[r][3] * inv;
        *(float4*)&yb[(size_t)(qbase + ty * 4 + r) * D_MODEL + tx * 4] = out4;
    }
}

// ---------------------------------------------------------------------------
// Launch: 3 sequential kernels on the default stream (graph-capturable,
// allocation-free, no syncs).
// ---------------------------------------------------------------------------
extern "C" void kernel_launch(void* const* d_in, const int* in_sizes, int n_in,
                              void* d_out, int out_size)
{
    (void)in_sizes; (void)n_in; (void)out_size;
    const float* x    = (const float*)d_in[0];
    const float* Wqkv = (const float*)d_in[1];
    const float* bqkv = (const float*)d_in[2];
    const float* Wout = (const float*)d_in[3];
    const float* bout = (const float*)d_in[4];
    float* out = (float*)d_out;

    // attention tile smem (69632B) exceeds the 48KB default dynamic limit
    cudaFuncSetAttribute(attn_kernel, cudaFuncAttributeMaxDynamicSharedMemorySize,
                         ATTN_SMEM_BYTES);

    dim3 g1(C3 / 128, MTOT / 128);           // 24 x 64
    qkv_gemm_kernel<<<g1, 256>>>(x, Wqkv, bqkv);

    dim3 g2(SEQ / 64, BATCH * N_HEADS);      // 32 x 64
    attn_kernel<<<g2, 256, ATTN_SMEM_BYTES>>>();

    dim3 g3(D_MODEL / 128, MTOT / 128);      // 8 x 64
    out_gemm_kernel<<<g3, 256>>>(Wout, bout, out);
}

// round 6
// speedup vs baseline: 1.1844x; 1.1844x over previous
#include <cuda_runtime.h>
#include <mma.h>

using namespace nvcuda;

// ---------------------------------------------------------------------------
// CausalSelfAttention: y = softmax_causal((xWqkv).q @ .k^T / sqrt(Dh)) @ .v @ Wout
// B=4, T=2048, C=1024, H=16, Dh=64.
// R3: dense GEMMs on TF32 tensor cores (wmma m16n16k8), attention still fp32.
// ---------------------------------------------------------------------------

#define D_MODEL 1024
#define N_HEADS 16
#define HEAD_DIM 64
#define BATCH 4
#define SEQ 2048
#define MTOT (BATCH * SEQ)   // 8192 rows
#define C3 (3 * D_MODEL)     // 3072

// Scratch (allocation-free rule: __device__ globals)
__device__ float g_qkv[(size_t)MTOT * C3];      // [B*T, 3C]   96 MB
__device__ float g_y[(size_t)MTOT * D_MODEL];   // [B*T, C]    32 MB

// ---------------------------------------------------------------------------
// TF32 GEMM: C[M,N] = A[M,K] @ B[K,N] + bias[N]
// Block tile 128x128, BK=32, 256 threads = 8 warps (2 M x 4 N).
// Warp tile 64x32 = 4x2 wmma 16x16x8 fragments, fp32 accumulate.
// M,N,K all multiples of 128/32 here -> no edge handling.
// ---------------------------------------------------------------------------
#define AS_LD 40    // 32 + 8 pad (float4-aligned, bank-shifted)
#define BS_LD 136   // 128 + 8 pad
#define EB_LD 24    // epilogue staging stride

__device__ __forceinline__ void tf32_gemm_body(const float* __restrict__ A,
                                               const float* __restrict__ B,
                                               const float* __restrict__ bias,
                                               float* __restrict__ C,
                                               int N, int K)
{
    __shared__ float As[128 * AS_LD];   // A tile [128][32] row-major (m-major)
    __shared__ float Bs[32 * BS_LD];    // B tile [32][128] row-major (k-major)

    const int tid  = threadIdx.x;
    const int lane = tid & 31;
    const int warp = tid >> 5;
    const int wm = warp >> 2;            // 0..1 : warp row (64 M each)
    const int wn = warp & 3;             // 0..3 : warp col (32 N each)

    const int bm = blockIdx.y * 128;
    const int bn = blockIdx.x * 128;

    // A loads: row = tid>>1 (0..127), 16 consecutive cols at (tid&1)*16
    const int aRow = tid >> 1;
    const int aCol = (tid & 1) * 16;
    // B loads: row = tid>>3 (0..31), 16 consecutive cols at (tid&7)*16
    const int bRow = tid >> 3;
    const int bCol = (tid & 7) * 16;

    const float* Ap = A + (size_t)(bm + aRow) * K + aCol;
    const float* Bp = B + (size_t)bRow * N + bn + bCol;

    wmma::fragment<wmma::accumulator, 16, 16, 8, float> acc[4][2];
#pragma unroll
    for (int i = 0; i < 4; i++)
#pragma unroll
        for (int j = 0; j < 2; j++) wmma::fill_fragment(acc[i][j], 0.0f);

    for (int k0 = 0; k0 < K; k0 += 32) {
        // ---- stage tiles into smem, converting to tf32 ----
#pragma unroll
        for (int v = 0; v < 4; v++) {
            float4 a4 = *(const float4*)(Ap + k0 + v * 4);
            float* d = &As[aRow * AS_LD + aCol + v * 4];
            d[0] = wmma::__float_to_tf32(a4.x);
            d[1] = wmma::__float_to_tf32(a4.y);
            d[2] = wmma::__float_to_tf32(a4.z);
            d[3] = wmma::__float_to_tf32(a4.w);
        }
#pragma unroll
        for (int v = 0; v < 4; v++) {
            float4 b4 = *(const float4*)(Bp + (size_t)k0 * N + v * 4);
            float* d = &Bs[bRow * BS_LD + bCol + v * 4];
            d[0] = wmma::__float_to_tf32(b4.x);
            d[1] = wmma::__float_to_tf32(b4.y);
            d[2] = wmma::__float_to_tf32(b4.z);
            d[3] = wmma::__float_to_tf32(b4.w);
        }
        __syncthreads();

        // ---- 4 k-steps of 8 ----
#pragma unroll
        for (int kk = 0; kk < 32; kk += 8) {
            wmma::fragment<wmma::matrix_b, 16, 16, 8, wmma::precision::tf32,
                           wmma::row_major> bf[2];
            wmma::load_matrix_sync(bf[0], &Bs[kk * BS_LD + wn * 32 + 0],  BS_LD);
            wmma::load_matrix_sync(bf[1], &Bs[kk * BS_LD + wn * 32 + 16], BS_LD);
#pragma unroll
            for (int i = 0; i < 4; i++) {
                wmma::fragment<wmma::matrix_a, 16, 16, 8, wmma::precision::tf32,
                               wmma::row_major> af;
                wmma::load_matrix_sync(af, &As[(wm * 64 + i * 16) * AS_LD + kk], AS_LD);
                wmma::mma_sync(acc[i][0], af, bf[0], acc[i][0]);
                wmma::mma_sync(acc[i][1], af, bf[1], acc[i][1]);
            }
        }
        __syncthreads();
    }

    // ---- epilogue: stage each 16x16 frag in per-warp smem, add bias, write ----
    float* eb = &As[warp * 16 * EB_LD];   // overlay on As (all reads done)
    const int er = lane >> 1;             // row 0..15 (2 lanes/row)
    const int ec = (lane & 1) * 8;        // col 0 or 8

#pragma unroll
    for (int i = 0; i < 4; i++) {
#pragma unroll
        for (int j = 0; j < 2; j++) {
            wmma::store_matrix_sync(eb, acc[i][j], EB_LD, wmma::mem_row_major);
            __syncwarp();
            const int row = bm + wm * 64 + i * 16 + er;
            const int col = bn + wn * 32 + j * 16 + ec;
            float4 v0 = *(const float4*)&eb[er * EB_LD + ec];
            float4 v1 = *(const float4*)&eb[er * EB_LD + ec + 4];
            float4 b0 = *(const float4*)&bias[col];
            float4 b1 = *(const float4*)&bias[col + 4];
            v0.x += b0.x; v0.y += b0.y; v0.z += b0.z; v0.w += b0.w;
            v1.x += b1.x; v1.y += b1.y; v1.z += b1.z; v1.w += b1.w;
            *(float4*)&C[(size_t)row * N + col]     = v0;
            *(float4*)&C[(size_t)row * N + col + 4] = v1;
            __syncwarp();
        }
    }
}

__global__ __launch_bounds__(256) void qkv_gemm_kernel(const float* __restrict__ x,
                                                       const float* __restrict__ W,
                                                       const float* __restrict__ bias)
{
    tf32_gemm_body(x, W, bias, g_qkv, C3, D_MODEL);
}

__global__ __launch_bounds__(256) void out_gemm_kernel(const float* __restrict__ W,
                                                       const float* __restrict__ bias,
                                                       float* __restrict__ out)
{
    tf32_gemm_body(g_y, W, bias, out, D_MODEL, D_MODEL);
}

// ---------------------------------------------------------------------------
// Flash attention (fp32, online softmax) — unchanged from R2 (passing, 1e-6).
// Grid: (T/64, B*H). Block: 256 threads = 16x16 grid of 4x4 microtiles.
// ---------------------------------------------------------------------------
#define APAD 68
#define ATTN_SMEM_BYTES (4 * 64 * APAD * (int)sizeof(float))  // 69632

__global__ __launch_bounds__(256) void attn_kernel()
{
    extern __shared__ float sm[];
    float* Qt = sm;                  // [64][APAD]
    float* Kt = Qt + 64 * APAD;
    float* Vs = Kt + 64 * APAD;
    float* Ps = Vs + 64 * APAD;

    const int qt = blockIdx.x;
    const int b  = blockIdx.y >> 4;
    const int h  = blockIdx.y & 15;
    const int tid = threadIdx.x;
    const int tx = tid & 15;
    const int ty = tid >> 4;
    const int qbase = qt * 64;

    const float* qkvb = g_qkv + (size_t)b * SEQ * C3 + h * HEAD_DIM;

    for (int idx = tid; idx < 64 * 64; idx += 256) {
        int i = idx >> 6, d = idx & 63;
        Qt[d * APAD + i] = qkvb[(size_t)(qbase + i) * C3 + d];
    }

    float m[4], l[4], o[4][4];
#pragma unroll
    for (int r = 0; r < 4; r++) {
        m[r] = -1e30f; l[r] = 0.0f;
#pragma unroll
        for (int c = 0; c < 4; c++) o[r][c] = 0.0f;
    }

    for (int kt = 0; kt <= qt; ++kt) {
        const int kbase = kt * 64;
        __syncthreads();
        for (int idx = tid; idx < 64 * 64; idx += 256) {
            int j = idx >> 6, d = idx & 63;
            size_t off = (size_t)(kbase + j) * C3 + d;
            Kt[d * APAD + j] = qkvb[off + D_MODEL];       // K
            Vs[j * APAD + d] = qkvb[off + 2 * D_MODEL];   // V
        }
        __syncthreads();

        float s[4][4];
#pragma unroll
        for (int r = 0; r < 4; r++)
#pragma unroll
            for (int c = 0; c < 4; c++) s[r][c] = 0.0f;

#pragma unroll 8
        for (int d = 0; d < 64; ++d) {
            float4 qv = *(const float4*)&Qt[d * APAD + ty * 4];
            float4 kv = *(const float4*)&Kt[d * APAD + tx * 4];
            float qa[4] = {qv.x, qv.y, qv.z, qv.w};
            float ka[4] = {kv.x, kv.y, kv.z, kv.w};
#pragma unroll
            for (int r = 0; r < 4; r++)
#pragma unroll
                for (int c = 0; c < 4; c++)
                    s[r][c] += qa[r] * ka[c];
        }

        const float scale = 0.125f;  // 1/sqrt(64)
        if (kt == qt) {
#pragma unroll
            for (int r = 0; r < 4; r++)
#pragma unroll
                for (int c = 0; c < 4; c++)
                    s[r][c] = (tx * 4 + c > ty * 4 + r) ? -1e30f : s[r][c] * scale;
        } else {
#pragma unroll
            for (int r = 0; r < 4; r++)
#pragma unroll
                for (int c = 0; c < 4; c++)
                    s[r][c] *= scale;
        }

#pragma unroll
        for (int r = 0; r < 4; r++) {
            float tm = fmaxf(fmaxf(s[r][0], s[r][1]), fmaxf(s[r][2], s[r][3]));
#pragma unroll
            for (int off = 8; off >= 1; off >>= 1)
                tm = fmaxf(tm, __shfl_xor_sync(0xffffffffu, tm, off));
            float nm = fmaxf(m[r], tm);
            float corr = __expf(m[r] - nm);
            m[r] = nm;
            float rs = 0.0f;
#pragma unroll
            for (int c = 0; c < 4; c++) {
                float p = __expf(s[r][c] - nm);
                s[r][c] = p;
                rs += p;
            }
#pragma unroll
            for (int off = 8; off >= 1; off >>= 1)
                rs += __shfl_xor_sync(0xffffffffu, rs, off);
            l[r] = l[r] * corr + rs;
#pragma unroll
            for (int c = 0; c < 4; c++) o[r][c] *= corr;
        }

#pragma unroll
        for (int r = 0; r < 4; r++)
#pragma unroll
            for (int c = 0; c < 4; c++)
                Ps[(ty * 4 + r) * APAD + tx * 4 + c] = s[r][c];
        __syncthreads();

#pragma unroll 8
        for (int j = 0; j < 64; ++j) {
            float4 vv = *(const float4*)&Vs[j * APAD + tx * 4];
            float va[4] = {vv.x, vv.y, vv.z, vv.w};
#pragma unroll
            for (int r = 0; r < 4; r++) {
                float p = Ps[(ty * 4 + r) * APAD + j];
#pragma unroll
                for (int c = 0; c < 4; c++)
                    o[r][c] += p * va[c];
            }
        }
    }

    float* yb = g_y + (size_t)b * SEQ * D_MODEL + h * HEAD_DIM;
#pragma unroll
    for (int r = 0; r < 4; r++) {
        float inv = 1.0f / l[r];
        float4 out4;
        out4.x = o[r][0] * inv;
        out4.y = o[r][1] * inv;
        out4.z = o[r][2] * inv;
        out4.w = o[r][3] * inv;
        *(float4*)&yb[(size_t)(qbase + ty * 4 + r) * D_MODEL + tx * 4] = out4;
    }
}

// ---------------------------------------------------------------------------
// Launch: 3 sequential kernels (graph-capturable, allocation-free, no syncs).
// ---------------------------------------------------------------------------
extern "C" void kernel_launch(void* const* d_in, const int* in_sizes, int n_in,
                              void* d_out, int out_size)
{
    (void)in_sizes; (void)n_in; (void)out_size;
    const float* x    = (const float*)d_in[0];
    const float* Wqkv = (const float*)d_in[1];
    const float* bqkv = (const float*)d_in[2];
    const float* Wout = (const float*)d_in[3];
    const float* bout = (const float*)d_in[4];
    float* out = (float*)d_out;

    cudaFuncSetAttribute(attn_kernel, cudaFuncAttributeMaxDynamicSharedMemorySize,
                         ATTN_SMEM_BYTES);

    dim3 g1(C3 / 128, MTOT / 128);           // 24 x 64
    qkv_gemm_kernel<<<g1, 256>>>(x, Wqkv, bqkv);

    dim3 g2(SEQ / 64, BATCH * N_HEADS);      // 32 x 64
    attn_kernel<<<g2, 256, ATTN_SMEM_BYTES>>>();

    dim3 g3(D_MODEL / 128, MTOT / 128);      // 8 x 64
    out_gemm_kernel<<<g3, 256>>>(Wout, bout, out);
}

// round 7
// speedup vs baseline: 1.2108x; 1.0223x over previous
#include <cuda_runtime.h>
#include <mma.h>

using namespace nvcuda;

// ---------------------------------------------------------------------------
// CausalSelfAttention  B=4, T=2048, C=1024, H=16, Dh=64
// R6: cp.async double-buffered TF32 GEMMs + TF32 wmma flash attention.
// ---------------------------------------------------------------------------

#define D_MODEL 1024
#define N_HEADS 16
#define HEAD_DIM 64
#define BATCH 4
#define SEQ 2048
#define MTOT (BATCH * SEQ)   // 8192
#define C3 (3 * D_MODEL)     // 3072

__device__ float g_qkv[(size_t)MTOT * C3];      // 96 MB
__device__ float g_y[(size_t)MTOT * D_MODEL];   // 32 MB

// ---------------- cp.async helpers ----------------
__device__ __forceinline__ void cp_async16(float* dst, const float* src) {
    unsigned s = (unsigned)__cvta_generic_to_shared(dst);
    asm volatile("cp.async.cg.shared.global [%0], [%1], 16;\n" :: "r"(s), "l"(src));
}
__device__ __forceinline__ void cp_commit() {
    asm volatile("cp.async.commit_group;\n" ::: "memory");
}
__device__ __forceinline__ void cp_wait1() {
    asm volatile("cp.async.wait_group 1;\n" ::: "memory");
}
__device__ __forceinline__ void cp_wait0() {
    asm volatile("cp.async.wait_group 0;\n" ::: "memory");
}

// ---------------------------------------------------------------------------
// TF32 GEMM: C[M,N] = A[M,K] @ B[K,N] + bias[N]
// 128x128 tile, BK=32, 256 thr = 8 warps (2M x 4N), warp tile 64x32.
// Double-buffered smem stages filled by cp.async; tf32 RN-cvt at frag load.
// ---------------------------------------------------------------------------
#define AS_LD 40
#define BS_LD 136
#define EB_LD 24
#define AS_STAGE (128 * AS_LD)
#define BS_STAGE (32 * BS_LD)
#define GEMM_SMEM_BYTES ((2 * (AS_STAGE + BS_STAGE)) * (int)sizeof(float))  // 75776

__device__ __forceinline__ void tf32_gemm_body(const float* __restrict__ A,
                                               const float* __restrict__ B,
                                               const float* __restrict__ bias,
                                               float* __restrict__ C,
                                               int N, int K)
{
    extern __shared__ float sm[];
    float* As0 = sm;                          // [2][128][AS_LD]
    float* Bs0 = sm + 2 * AS_STAGE;           // [2][32][BS_LD]

    const int tid  = threadIdx.x;
    const int lane = tid & 31;
    const int warp = tid >> 5;
    const int wm = warp >> 2;            // 0..1
    const int wn = warp & 3;             // 0..3

    const int bm = blockIdx.y * 128;
    const int bn = blockIdx.x * 128;

    const int aRow = tid >> 1;            // 0..127
    const int aCol = (tid & 1) * 16;      // 0 or 16
    const int bRow = tid >> 3;            // 0..31
    const int bCol = (tid & 7) * 16;      // 0..112

    const float* Ap = A + (size_t)(bm + aRow) * K + aCol;
    const float* Bp = B + (size_t)bRow * N + bn + bCol;

    wmma::fragment<wmma::accumulator, 16, 16, 8, float> acc[4][2];
#pragma unroll
    for (int i = 0; i < 4; i++)
#pragma unroll
        for (int j = 0; j < 2; j++) wmma::fill_fragment(acc[i][j], 0.0f);

    // ---- stage issue lambda-equivalent ----
#define GEMM_STAGE(buf, k0)                                                     \
    do {                                                                        \
        float* Asb = As0 + (buf) * AS_STAGE;                                    \
        float* Bsb = Bs0 + (buf) * BS_STAGE;                                    \
        const float* ag = Ap + (k0);                                            \
        const float* bg = Bp + (size_t)(k0) * N;                                \
        _Pragma("unroll")                                                       \
        for (int v = 0; v < 4; v++)                                             \
            cp_async16(&Asb[aRow * AS_LD + aCol + v * 4], ag + v * 4);          \
        _Pragma("unroll")                                                       \
        for (int v = 0; v < 4; v++)                                             \
            cp_async16(&Bsb[bRow * BS_LD + bCol + v * 4], bg + v * 4);          \
    } while (0)

    GEMM_STAGE(0, 0);
    cp_commit();

    int buf = 0;
    for (int k0 = 0; k0 < K; k0 += 32) {
        if (k0 + 32 < K) {
            GEMM_STAGE(buf ^ 1, k0 + 32);
            cp_commit();
            cp_wait1();
        } else {
            cp_wait0();
        }
        __syncthreads();

        const float* Asb = As0 + buf * AS_STAGE;
        const float* Bsb = Bs0 + buf * BS_STAGE;

#pragma unroll
        for (int kk = 0; kk < 32; kk += 8) {
            wmma::fragment<wmma::matrix_b, 16, 16, 8, wmma::precision::tf32,
                           wmma::row_major> bf[2];
            wmma::load_matrix_sync(bf[0], &Bsb[kk * BS_LD + wn * 32 + 0],  BS_LD);
            wmma::load_matrix_sync(bf[1], &Bsb[kk * BS_LD + wn * 32 + 16], BS_LD);
#pragma unroll
            for (int t = 0; t < bf[0].num_elements; t++) {
                bf[0].x[t] = wmma::__float_to_tf32(bf[0].x[t]);
                bf[1].x[t] = wmma::__float_to_tf32(bf[1].x[t]);
            }
#pragma unroll
            for (int i = 0; i < 4; i++) {
                wmma::fragment<wmma::matrix_a, 16, 16, 8, wmma::precision::tf32,
                               wmma::row_major> af;
                wmma::load_matrix_sync(af, &Asb[(wm * 64 + i * 16) * AS_LD + kk], AS_LD);
#pragma unroll
                for (int t = 0; t < af.num_elements; t++)
                    af.x[t] = wmma::__float_to_tf32(af.x[t]);
                wmma::mma_sync(acc[i][0], af, bf[0], acc[i][0]);
                wmma::mma_sync(acc[i][1], af, bf[1], acc[i][1]);
            }
        }
        __syncthreads();
        buf ^= 1;
    }
#undef GEMM_STAGE

    // ---- epilogue: per-warp smem staging + bias ----
    float* eb = &As0[warp * 16 * EB_LD];
    const int er = lane >> 1;
    const int ec = (lane & 1) * 8;

#pragma unroll
    for (int i = 0; i < 4; i++) {
#pragma unroll
        for (int j = 0; j < 2; j++) {
            wmma::store_matrix_sync(eb, acc[i][j], EB_LD, wmma::mem_row_major);
            __syncwarp();
            const int row = bm + wm * 64 + i * 16 + er;
            const int col = bn + wn * 32 + j * 16 + ec;
            float4 v0 = *(const float4*)&eb[er * EB_LD + ec];
            float4 v1 = *(const float4*)&eb[er * EB_LD + ec + 4];
            float4 b0 = *(const float4*)&bias[col];
            float4 b1 = *(const float4*)&bias[col + 4];
            v0.x += b0.x; v0.y += b0.y; v0.z += b0.z; v0.w += b0.w;
            v1.x += b1.x; v1.y += b1.y; v1.z += b1.z; v1.w += b1.w;
            *(float4*)&C[(size_t)row * N + col]     = v0;
            *(float4*)&C[(size_t)row * N + col + 4] = v1;
            __syncwarp();
        }
    }
}

__global__ __launch_bounds__(256) void qkv_gemm_kernel(const float* __restrict__ x,
                                                       const float* __restrict__ W,
                                                       const float* __restrict__ bias)
{
    tf32_gemm_body(x, W, bias, g_qkv, C3, D_MODEL);
}

__global__ __launch_bounds__(256) void out_gemm_kernel(const float* __restrict__ W,
                                                       const float* __restrict__ bias,
                                                       float* __restrict__ out)
{
    tf32_gemm_body(g_y, W, bias, out, D_MODEL, D_MODEL);
}

// ---------------------------------------------------------------------------
// TF32 tensor-core flash attention.
// Grid (T/64, B*H). Block 256 thr = 8 warps.
// Warp w: S/O rows 16*(w&3), S cols / O cols 32*(w>>2).
// Smem (all ld=72, natural layouts — no transposes):
//   Qs[i][d], Ks[j][d] (B frag col_major), Vs[j][d], Ss[i][j] (S/P),
//   Os[i][d] (fp32 running O), Ks reused to stage the P@V partial.
// ---------------------------------------------------------------------------
#define APAD 72
#define ATILE (64 * APAD)
#define ATTN_SMEM_BYTES ((5 * ATILE + 3 * 64) * (int)sizeof(float))  // ~92.9 KB

__global__ __launch_bounds__(256) void attn_kernel()
{
    extern __shared__ float sm[];
    float* Qs = sm;
    float* Ks = Qs + ATILE;
    float* Vs = Ks + ATILE;
    float* Ss = Vs + ATILE;
    float* Os = Ss + ATILE;
    float* m_s    = Os + ATILE;       // [64]
    float* l_s    = m_s + 64;
    float* corr_s = l_s + 64;

    const int qt = blockIdx.x;
    const int b  = blockIdx.y >> 4;
    const int h  = blockIdx.y & 15;
    const int tid  = threadIdx.x;
    const int warp = tid >> 5;
    const int sr = (warp & 3) * 16;       // row base
    const int sc = (warp >> 2) * 32;      // S col base / O col base
    const int qbase = qt * 64;

    const float* qkvb = g_qkv + (size_t)b * SEQ * C3 + h * HEAD_DIM;

    // Load Q tile [i][d] + init stats/O
    for (int idx = tid; idx < 64 * 16; idx += 256) {
        int i = idx >> 4, d4 = (idx & 15) * 4;
        *(float4*)&Qs[i * APAD + d4] =
            *(const float4*)&qkvb[(size_t)(qbase + i) * C3 + d4];
        *(float4*)&Os[i * APAD + d4] = make_float4(0.f, 0.f, 0.f, 0.f);
    }
    if (tid < 64) { m_s[tid] = -1e30f; l_s[tid] = 0.0f; }

    for (int kt = 0; kt <= qt; ++kt) {
        const int kbase = kt * 64;
        __syncthreads();   // Ks/Vs free (prev iter O-update read Ks)

        for (int idx = tid; idx < 64 * 16; idx += 256) {
            int j = idx >> 4, d4 = (idx & 15) * 4;
            size_t off = (size_t)(kbase + j) * C3 + d4;
            *(float4*)&Ks[j * APAD + d4] = *(const float4*)&qkvb[off + D_MODEL];
            *(float4*)&Vs[j * APAD + d4] = *(const float4*)&qkvb[off + 2 * D_MODEL];
        }
        __syncthreads();

        // ---- S = Q @ K^T (tf32 wmma). B = K^T via col_major on Ks[j][d]. ----
        {
            wmma::fragment<wmma::accumulator, 16, 16, 8, float> sacc[2];
            wmma::fill_fragment(sacc[0], 0.0f);
            wmma::fill_fragment(sacc[1], 0.0f);
#pragma unroll
            for (int kk = 0; kk < 64; kk += 8) {
                wmma::fragment<wmma::matrix_a, 16, 16, 8, wmma::precision::tf32,
                               wmma::row_major> af;
                wmma::load_matrix_sync(af, &Qs[sr * APAD + kk], APAD);
#pragma unroll
                for (int t = 0; t < af.num_elements; t++)
                    af.x[t] = wmma::__float_to_tf32(af.x[t]);
                wmma::fragment<wmma::matrix_b, 16, 16, 8, wmma::precision::tf32,
                               wmma::col_major> bf0, bf1;
                wmma::load_matrix_sync(bf0, &Ks[(sc + 0)  * APAD + kk], APAD);
                wmma::load_matrix_sync(bf1, &Ks[(sc + 16) * APAD + kk], APAD);
#pragma unroll
                for (int t = 0; t < bf0.num_elements; t++) {
                    bf0.x[t] = wmma::__float_to_tf32(bf0.x[t]);
                    bf1.x[t] = wmma::__float_to_tf32(bf1.x[t]);
                }
                wmma::mma_sync(sacc[0], af, bf0, sacc[0]);
                wmma::mma_sync(sacc[1], af, bf1, sacc[1]);
            }
            wmma::store_matrix_sync(&Ss[sr * APAD + sc],      sacc[0], APAD,
                                    wmma::mem_row_major);
            wmma::store_matrix_sync(&Ss[sr * APAD + sc + 16], sacc[1], APAD,
                                    wmma::mem_row_major);
        }
        __syncthreads();

        // ---- online softmax on Ss (fp32). 4 threads per row, 16 cols each ----
        {
            const int r   = tid >> 2;
            const int c16 = (tid & 3) * 16;
            const float scale = 0.125f;   // 1/sqrt(64)
            float sv[16];
            float tmax = -1e30f;
#pragma unroll
            for (int c = 0; c < 16; c++) {
                float s = Ss[r * APAD + c16 + c] * scale;
                if (kt == qt && (c16 + c) > r) s = -1e30f;   // causal mask (diag tile)
                sv[c] = s;
                tmax = fmaxf(tmax, s);
            }
            tmax = fmaxf(tmax, __shfl_xor_sync(0xffffffffu, tmax, 1));
            tmax = fmaxf(tmax, __shfl_xor_sync(0xffffffffu, tmax, 2));
            const float mold = m_s[r];
            const float nm = fmaxf(mold, tmax);
            float rs = 0.0f;
#pragma unroll
            for (int c = 0; c < 16; c++) {
                float p = __expf(sv[c] - nm);
                Ss[r * APAD + c16 + c] = p;
                rs += p;
            }
            rs += __shfl_xor_sync(0xffffffffu, rs, 1);
            rs += __shfl_xor_sync(0xffffffffu, rs, 2);
            if ((tid & 3) == 0) {
                const float corr = __expf(mold - nm);
                m_s[r] = nm;
                l_s[r] = l_s[r] * corr + rs;
                corr_s[r] = corr;
            }
        }
        __syncthreads();

        // ---- PV = P @ V (tf32 wmma); stage result into Ks (free now) ----
        {
            wmma::fragment<wmma::accumulator, 16, 16, 8, float> oacc[2];
            wmma::fill_fragment(oacc[0], 0.0f);
            wmma::fill_fragment(oacc[1], 0.0f);
#pragma unroll
            for (int kk = 0; kk < 64; kk += 8) {
                wmma::fragment<wmma::matrix_a, 16, 16, 8, wmma::precision::tf32,
                               wmma::row_major> af;
                wmma::load_matrix_sync(af, &Ss[sr * APAD + kk], APAD);
#pragma unroll
                for (int t = 0; t < af.num_elements; t++)
                    af.x[t] = wmma::__float_to_tf32(af.x[t]);
                wmma::fragment<wmma::matrix_b, 16, 16, 8, wmma::precision::tf32,
                               wmma::row_major> bf0, bf1;
                wmma::load_matrix_sync(bf0, &Vs[kk * APAD + sc],      APAD);
                wmma::load_matrix_sync(bf1, &Vs[kk * APAD + sc + 16], APAD);
#pragma unroll
                for (int t = 0; t < bf0.num_elements; t++) {
                    bf0.x[t] = wmma::__float_to_tf32(bf0.x[t]);
                    bf1.x[t] = wmma::__float_to_tf32(bf1.x[t]);
                }
                wmma::mma_sync(oacc[0], af, bf0, oacc[0]);
                wmma::mma_sync(oacc[1], af, bf1, oacc[1]);
            }
            wmma::store_matrix_sync(&Ks[sr * APAD + sc],      oacc[0], APAD,
                                    wmma::mem_row_major);
            wmma::store_matrix_sync(&Ks[sr * APAD + sc + 16], oacc[1], APAD,
                                    wmma::mem_row_major);
        }
        __syncthreads();

        // ---- O = O * corr + PV ----
        for (int idx = tid; idx < 64 * 16; idx += 256) {
            int i = idx >> 4, d4 = (idx & 15) * 4;
            float corr = corr_s[i];
            float4 o = *(float4*)&Os[i * APAD + d4];
            float4 p = *(const float4*)&Ks[i * APAD + d4];
            o.x = o.x * corr + p.x;
            o.y = o.y * corr + p.y;
            o.z = o.z * corr + p.z;
            o.w = o.w * corr + p.w;
            *(float4*)&Os[i * APAD + d4] = o;
        }
    }
    __syncthreads();

    // ---- finalize: y[b, qbase+i, h*64 + d] = O[i][d] / l[i] ----
    float* yb = g_y + (size_t)b * SEQ * D_MODEL + h * HEAD_DIM;
    for (int idx = tid; idx < 64 * 16; idx += 256) {
        int i = idx >> 4, d4 = (idx & 15) * 4;
        float inv = 1.0f / l_s[i];
        float4 o = *(const float4*)&Os[i * APAD + d4];
        o.x *= inv; o.y *= inv; o.z *= inv; o.w *= inv;
        *(float4*)&yb[(size_t)(qbase + i) * D_MODEL + d4] = o;
    }
}

// ---------------------------------------------------------------------------
// Launch (graph-capturable, allocation-free, no syncs)
// ---------------------------------------------------------------------------
extern "C" void kernel_launch(void* const* d_in, const int* in_sizes, int n_in,
                              void* d_out, int out_size)
{
    (void)in_sizes; (void)n_in; (void)out_size;
    const float* x    = (const float*)d_in[0];
    const float* Wqkv = (const float*)d_in[1];
    const float* bqkv = (const float*)d_in[2];
    const float* Wout = (const float*)d_in[3];
    const float* bout = (const float*)d_in[4];
    float* out = (float*)d_out;

    cudaFuncSetAttribute(qkv_gemm_kernel, cudaFuncAttributeMaxDynamicSharedMemorySize,
                         GEMM_SMEM_BYTES);
    cudaFuncSetAttribute(out_gemm_kernel, cudaFuncAttributeMaxDynamicSharedMemorySize,
                         GEMM_SMEM_BYTES);
    cudaFuncSetAttribute(attn_kernel, cudaFuncAttributeMaxDynamicSharedMemorySize,
                         ATTN_SMEM_BYTES);

    dim3 g1(C3 / 128, MTOT / 128);           // 24 x 64
    qkv_gemm_kernel<<<g1, 256, GEMM_SMEM_BYTES>>>(x, Wqkv, bqkv);

    dim3 g2(SEQ / 64, BATCH * N_HEADS);      // 32 x 64
    attn_kernel<<<g2, 256, ATTN_SMEM_BYTES>>>();

    dim3 g3(D_MODEL / 128, MTOT / 128);      // 8 x 64
    out_gemm_kernel<<<g3, 256, GEMM_SMEM_BYTES>>>(Wout, bout, out);
}

// round 12
// speedup vs baseline: 1.2915x; 1.0666x over previous
#include <cuda_runtime.h>
#include <mma.h>
#include <cstdint>

using namespace nvcuda;

// ---------------------------------------------------------------------------
// CausalSelfAttention  B=4, T=2048, C=1024, H=16, Dh=64
// R11: maximum-robustness recombination of proven-passing parts.
//   GEMMs: R3 tf32 wmma (cvt at staging, single-buffer) — measured 889/296us.
//   Attention: R6 wmma structure (passed) + cvt moved to staging.
//   No cp.async, no launch_bounds minBlocks, no tcgen05 (not compilable here).
// ---------------------------------------------------------------------------

#define D_MODEL 1024
#define N_HEADS 16
#define HEAD_DIM 64
#define BATCH 4
#define SEQ 2048
#define MTOT (BATCH * SEQ)   // 8192
#define C3 (3 * D_MODEL)     // 3072

__device__ float g_qkv[(size_t)MTOT * C3];      // 96 MB
__device__ float g_y[(size_t)MTOT * D_MODEL];   // 32 MB

// ---------------------------------------------------------------------------
// TF32 GEMM (R3, proven): C[M,N] = A[M,K] @ B[K,N] + bias[N]
// 128x128 tile, BK=32, 256 thr = 8 warps (2M x 4N), warp tile 64x32.
// tf32 RN conversion at smem staging.
// ---------------------------------------------------------------------------
#define AS_LD 40    // 32 + 8 pad
#define BS_LD 136   // 128 + 8 pad
#define EB_LD 24    // epilogue staging stride

__device__ __forceinline__ void tf32_gemm_body(const float* __restrict__ A,
                                               const float* __restrict__ B,
                                               const float* __restrict__ bias,
                                               float* __restrict__ C,
                                               int N, int K)
{
    __shared__ float As[128 * AS_LD];   // A tile [128][32]
    __shared__ float Bs[32 * BS_LD];    // B tile [32][128]

    const int tid  = threadIdx.x;
    const int lane = tid & 31;
    const int warp = tid >> 5;
    const int wm = warp >> 2;            // 0..1
    const int wn = warp & 3;             // 0..3

    const int bm = blockIdx.y * 128;
    const int bn = blockIdx.x * 128;

    const int aRow = tid >> 1;
    const int aCol = (tid & 1) * 16;
    const int bRow = tid >> 3;
    const int bCol = (tid & 7) * 16;

    const float* Ap = A + (size_t)(bm + aRow) * K + aCol;
    const float* Bp = B + (size_t)bRow * N + bn + bCol;

    wmma::fragment<wmma::accumulator, 16, 16, 8, float> acc[4][2];
#pragma unroll
    for (int i = 0; i < 4; i++)
#pragma unroll
        for (int j = 0; j < 2; j++) wmma::fill_fragment(acc[i][j], 0.0f);

    for (int k0 = 0; k0 < K; k0 += 32) {
#pragma unroll
        for (int v = 0; v < 4; v++) {
            float4 a4 = *(const float4*)(Ap + k0 + v * 4);
            float* d = &As[aRow * AS_LD + aCol + v * 4];
            d[0] = wmma::__float_to_tf32(a4.x);
            d[1] = wmma::__float_to_tf32(a4.y);
            d[2] = wmma::__float_to_tf32(a4.z);
            d[3] = wmma::__float_to_tf32(a4.w);
        }
#pragma unroll
        for (int v = 0; v < 4; v++) {
            float4 b4 = *(const float4*)(Bp + (size_t)k0 * N + v * 4);
            float* d = &Bs[bRow * BS_LD + bCol + v * 4];
            d[0] = wmma::__float_to_tf32(b4.x);
            d[1] = wmma::__float_to_tf32(b4.y);
            d[2] = wmma::__float_to_tf32(b4.z);
            d[3] = wmma::__float_to_tf32(b4.w);
        }
        __syncthreads();

#pragma unroll
        for (int kk = 0; kk < 32; kk += 8) {
            wmma::fragment<wmma::matrix_b, 16, 16, 8, wmma::precision::tf32,
                           wmma::row_major> bf[2];
            wmma::load_matrix_sync(bf[0], &Bs[kk * BS_LD + wn * 32 + 0],  BS_LD);
            wmma::load_matrix_sync(bf[1], &Bs[kk * BS_LD + wn * 32 + 16], BS_LD);
#pragma unroll
            for (int i = 0; i < 4; i++) {
                wmma::fragment<wmma::matrix_a, 16, 16, 8, wmma::precision::tf32,
                               wmma::row_major> af;
                wmma::load_matrix_sync(af, &As[(wm * 64 + i * 16) * AS_LD + kk], AS_LD);
                wmma::mma_sync(acc[i][0], af, bf[0], acc[i][0]);
                wmma::mma_sync(acc[i][1], af, bf[1], acc[i][1]);
            }
        }
        __syncthreads();
    }

    // ---- epilogue: per-warp smem staging + bias ----
    float* eb = &As[warp * 16 * EB_LD];
    const int er = lane >> 1;
    const int ec = (lane & 1) * 8;

#pragma unroll
    for (int i = 0; i < 4; i++) {
#pragma unroll
        for (int j = 0; j < 2; j++) {
            wmma::store_matrix_sync(eb, acc[i][j], EB_LD, wmma::mem_row_major);
            __syncwarp();
            const int row = bm + wm * 64 + i * 16 + er;
            const int col = bn + wn * 32 + j * 16 + ec;
            float4 v0 = *(const float4*)&eb[er * EB_LD + ec];
            float4 v1 = *(const float4*)&eb[er * EB_LD + ec + 4];
            float4 b0 = *(const float4*)&bias[col];
            float4 b1 = *(const float4*)&bias[col + 4];
            v0.x += b0.x; v0.y += b0.y; v0.z += b0.z; v0.w += b0.w;
            v1.x += b1.x; v1.y += b1.y; v1.z += b1.z; v1.w += b1.w;
            *(float4*)&C[(size_t)row * N + col]     = v0;
            *(float4*)&C[(size_t)row * N + col + 4] = v1;
            __syncwarp();
        }
    }
}

__global__ __launch_bounds__(256) void qkv_gemm_kernel(const float* __restrict__ x,
                                                       const float* __restrict__ W,
                                                       const float* __restrict__ bias)
{
    tf32_gemm_body(x, W, bias, g_qkv, C3, D_MODEL);
}

__global__ __launch_bounds__(256) void out_gemm_kernel(const float* __restrict__ W,
                                                       const float* __restrict__ bias,
                                                       float* __restrict__ out)
{
    tf32_gemm_body(g_y, W, bias, out, D_MODEL, D_MODEL);
}

// ---------------------------------------------------------------------------
// TF32 wmma flash attention (R6 structure; tf32 cvt at smem staging).
// Grid (T/64, B*H). Block 256 thr = 8 warps.
// ---------------------------------------------------------------------------
#define APAD 72
#define ATILE (64 * APAD)
#define ATTN_SMEM_BYTES ((5 * ATILE + 3 * 64) * (int)sizeof(float))

__global__ __launch_bounds__(256) void attn_kernel()
{
    extern __shared__ float sm[];
    float* Qs = sm;
    float* Ks = Qs + ATILE;
    float* Vs = Ks + ATILE;
    float* Ss = Vs + ATILE;
    float* Os = Ss + ATILE;
    float* m_s    = Os + ATILE;
    float* l_s    = m_s + 64;
    float* corr_s = l_s + 64;

    const int qt = blockIdx.x;
    const int b  = blockIdx.y >> 4;
    const int h  = blockIdx.y & 15;
    const int tid  = threadIdx.x;
    const int warp = tid >> 5;
    const int sr = (warp & 3) * 16;
    const int sc = (warp >> 2) * 32;
    const int qbase = qt * 64;

    const float* qkvb = g_qkv + (size_t)b * SEQ * C3 + h * HEAD_DIM;

    for (int idx = tid; idx < 64 * 16; idx += 256) {
        int i = idx >> 4, d4 = (idx & 15) * 4;
        float4 q = *(const float4*)&qkvb[(size_t)(qbase + i) * C3 + d4];
        q.x = wmma::__float_to_tf32(q.x);
        q.y = wmma::__float_to_tf32(q.y);
        q.z = wmma::__float_to_tf32(q.z);
        q.w = wmma::__float_to_tf32(q.w);
        *(float4*)&Qs[i * APAD + d4] = q;
        *(float4*)&Os[i * APAD + d4] = make_float4(0.f, 0.f, 0.f, 0.f);
    }
    if (tid < 64) { m_s[tid] = -1e30f; l_s[tid] = 0.0f; }

    for (int kt = 0; kt <= qt; ++kt) {
        const int kbase = kt * 64;
        __syncthreads();

        for (int idx = tid; idx < 64 * 16; idx += 256) {
            int j = idx >> 4, d4 = (idx & 15) * 4;
            size_t off = (size_t)(kbase + j) * C3 + d4;
            float4 k = *(const float4*)&qkvb[off + D_MODEL];
            float4 v = *(const float4*)&qkvb[off + 2 * D_MODEL];
            k.x = wmma::__float_to_tf32(k.x);
            k.y = wmma::__float_to_tf32(k.y);
            k.z = wmma::__float_to_tf32(k.z);
            k.w = wmma::__float_to_tf32(k.w);
            v.x = wmma::__float_to_tf32(v.x);
            v.y = wmma::__float_to_tf32(v.y);
            v.z = wmma::__float_to_tf32(v.z);
            v.w = wmma::__float_to_tf32(v.w);
            *(float4*)&Ks[j * APAD + d4] = k;
            *(float4*)&Vs[j * APAD + d4] = v;
        }
        __syncthreads();

        // ---- S = Q @ K^T ----
        {
            wmma::fragment<wmma::accumulator, 16, 16, 8, float> sacc[2];
            wmma::fill_fragment(sacc[0], 0.0f);
            wmma::fill_fragment(sacc[1], 0.0f);
#pragma unroll
            for (int kk = 0; kk < 64; kk += 8) {
                wmma::fragment<wmma::matrix_a, 16, 16, 8, wmma::precision::tf32,
                               wmma::row_major> af;
                wmma::load_matrix_sync(af, &Qs[sr * APAD + kk], APAD);
                wmma::fragment<wmma::matrix_b, 16, 16, 8, wmma::precision::tf32,
                               wmma::col_major> bf0, bf1;
                wmma::load_matrix_sync(bf0, &Ks[(sc + 0)  * APAD + kk], APAD);
                wmma::load_matrix_sync(bf1, &Ks[(sc + 16) * APAD + kk], APAD);
                wmma::mma_sync(sacc[0], af, bf0, sacc[0]);
                wmma::mma_sync(sacc[1], af, bf1, sacc[1]);
            }
            wmma::store_matrix_sync(&Ss[sr * APAD + sc],      sacc[0], APAD,
                                    wmma::mem_row_major);
            wmma::store_matrix_sync(&Ss[sr * APAD + sc + 16], sacc[1], APAD,
                                    wmma::mem_row_major);
        }
        __syncthreads();

        // ---- online softmax (4 threads/row, 16 cols each) ----
        {
            const int r   = tid >> 2;
            const int c16 = (tid & 3) * 16;
            const float scale = 0.125f;
            float sv[16];
            float tmax = -1e30f;
#pragma unroll
            for (int c = 0; c < 16; c++) {
                float s = Ss[r * APAD + c16 + c] * scale;
                if (kt == qt && (c16 + c) > r) s = -1e30f;
                sv[c] = s;
                tmax = fmaxf(tmax, s);
            }
            tmax = fmaxf(tmax, __shfl_xor_sync(0xffffffffu, tmax, 1));
            tmax = fmaxf(tmax, __shfl_xor_sync(0xffffffffu, tmax, 2));
            const float mold = m_s[r];
            const float nm = fmaxf(mold, tmax);
            float rs = 0.0f;
#pragma unroll
            for (int c = 0; c < 16; c++) {
                float p = __expf(sv[c] - nm);
                Ss[r * APAD + c16 + c] = wmma::__float_to_tf32(p);
                rs += p;
            }
            rs += __shfl_xor_sync(0xffffffffu, rs, 1);
            rs += __shfl_xor_sync(0xffffffffu, rs, 2);
            if ((tid & 3) == 0) {
                const float corr = __expf(mold - nm);
                m_s[r] = nm;
                l_s[r] = l_s[r] * corr + rs;
                corr_s[r] = corr;
            }
        }
        __syncthreads();

        // ---- PV = P @ V; stage into Ks (free now) ----
        {
            wmma::fragment<wmma::accumulator, 16, 16, 8, float> oacc[2];
            wmma::fill_fragment(oacc[0], 0.0f);
            wmma::fill_fragment(oacc[1], 0.0f);
#pragma unroll
            for (int kk = 0; kk < 64; kk += 8) {
                wmma::fragment<wmma::matrix_a, 16, 16, 8, wmma::precision::tf32,
                               wmma::row_major> af;
                wmma::load_matrix_sync(af, &Ss[sr * APAD + kk], APAD);
                wmma::fragment<wmma::matrix_b, 16, 16, 8, wmma::precision::tf32,
                               wmma::row_major> bf0, bf1;
                wmma::load_matrix_sync(bf0, &Vs[kk * APAD + sc],      APAD);
                wmma::load_matrix_sync(bf1, &Vs[kk * APAD + sc + 16], APAD);
                wmma::mma_sync(oacc[0], af, bf0, oacc[0]);
                wmma::mma_sync(oacc[1], af, bf1, oacc[1]);
            }
            wmma::store_matrix_sync(&Ks[sr * APAD + sc],      oacc[0], APAD,
                                    wmma::mem_row_major);
            wmma::store_matrix_sync(&Ks[sr * APAD + sc + 16], oacc[1], APAD,
                                    wmma::mem_row_major);
        }
        __syncthreads();

        // ---- O = O * corr + PV ----
        for (int idx = tid; idx < 64 * 16; idx += 256) {
            int i = idx >> 4, d4 = (idx & 15) * 4;
            float corr = corr_s[i];
            float4 o = *(float4*)&Os[i * APAD + d4];
            float4 p = *(const float4*)&Ks[i * APAD + d4];
            o.x = o.x * corr + p.x;
            o.y = o.y * corr + p.y;
            o.z = o.z * corr + p.z;
            o.w = o.w * corr + p.w;
            *(float4*)&Os[i * APAD + d4] = o;
        }
    }
    __syncthreads();

    float* yb = g_y + (size_t)b * SEQ * D_MODEL + h * HEAD_DIM;
    for (int idx = tid; idx < 64 * 16; idx += 256) {
        int i = idx >> 4, d4 = (idx & 15) * 4;
        float inv = 1.0f / l_s[i];
        float4 o = *(const float4*)&Os[i * APAD + d4];
        o.x *= inv; o.y *= inv; o.z *= inv; o.w *= inv;
        *(float4*)&yb[(size_t)(qbase + i) * D_MODEL + d4] = o;
    }
}

// ---------------------------------------------------------------------------
// Launch (graph-capturable, allocation-free, no syncs)
// ---------------------------------------------------------------------------
extern "C" void kernel_launch(void* const* d_in, const int* in_sizes, int n_in,
                              void* d_out, int out_size)
{
    (void)in_sizes; (void)n_in; (void)out_size;
    const float* x    = (const float*)d_in[0];
    const float* Wqkv = (const float*)d_in[1];
    const float* bqkv = (const float*)d_in[2];
    const float* Wout = (const float*)d_in[3];
    const float* bout = (const float*)d_in[4];
    float* out = (float*)d_out;

    cudaFuncSetAttribute(attn_kernel, cudaFuncAttributeMaxDynamicSharedMemorySize,
                         ATTN_SMEM_BYTES);

    dim3 g1(C3 / 128, MTOT / 128);           // 24 x 64
    qkv_gemm_kernel<<<g1, 256>>>(x, Wqkv, bqkv);

    dim3 g2(SEQ / 64, BATCH * N_HEADS);      // 32 x 64
    attn_kernel<<<g2, 256, ATTN_SMEM_BYTES>>>();

    dim3 g3(D_MODEL / 128, MTOT / 128);      // 8 x 64
    out_gemm_kernel<<<g3, 256>>>(Wout, bout, out);
}